// round 15
// baseline (speedup 1.0000x reference)
#include <cuda_runtime.h>
#include <cstdint>

#define BB 16
#define CC 64
#define HH 32
#define WW 32
#define TT 30
#define TP 32
#define HO 16
#define WO 16

// ---- scratch (static device memory; no allocations) ----
__device__ float g_sf[BB*CC*HH*WW*TP];   // spikes s_a as float (t padded to 32)
__device__ float g_za[BB*CC*HH*WW];
__device__ float g_zb[BB*CC*HO*WO];
__device__ float g_ubar[BB*CC*HH*WW];

// pre-interleaved weights
__device__ __align__(16) float g_wA [16*4608];   // finalA: [cc][ci4][tap9][pair32][4]
__device__ __align__(16) float g_wB [16*4608];   // finalB: same layout (Wdn/Wbb)
__device__ __align__(16) float g_wC1[2*18432];   // conv1:  [cg][(ci*9+tap)*32+co]
__device__ __align__(16) float g_wC2[2*18432];   // conv2:  same (Wdn)

// packed f32x2 helpers
static __device__ __forceinline__ unsigned long long pk2(float x) {
    unsigned long long r;
    asm("mov.b64 %0, {%1, %1};" : "=l"(r) : "f"(x));
    return r;
}
static __device__ __forceinline__ unsigned long long fma2(unsigned long long a,
                                                          unsigned long long b,
                                                          unsigned long long c) {
    unsigned long long d;
    asm("fma.rn.f32x2 %0, %1, %2, %3;" : "=l"(d) : "l"(a), "l"(b), "l"(c));
    return d;
}
static __device__ __forceinline__ void unpk2(unsigned long long v, float& lo, float& hi) {
    asm("mov.b64 {%0, %1}, %2;" : "=f"(lo), "=f"(hi) : "l"(v));
}

// cp.async helpers
static __device__ __forceinline__ void cpa4(unsigned int dst, const void* src, bool ok) {
    asm volatile("cp.async.ca.shared.global [%0], [%1], 4, %2;"
                 :: "r"(dst), "l"(src), "r"(ok ? 4u : 0u));
}
static __device__ __forceinline__ void cpa16(unsigned int dst, const void* src) {
    asm volatile("cp.async.cg.shared.global [%0], [%1], 16;" :: "r"(dst), "l"(src));
}
static __device__ __forceinline__ unsigned int smaddr(const void* p) {
    return (unsigned int)__cvta_generic_to_shared(p);
}
#define CP_COMMIT() asm volatile("cp.async.commit_group;" ::: "memory")

// ============================================================
// weight prep: scatter-read once, so every consumer does coalesced loads
// ============================================================
__global__ __launch_bounds__(256) void wprep_k(const float* __restrict__ Win,
                                               const float* __restrict__ Waa,
                                               const float* __restrict__ Wdn,
                                               const float* __restrict__ Wbb)
{
    int idx = blockIdx.x * 256 + threadIdx.x;
    if (idx < 147456) {                      // g_wA / g_wB (pair-interleaved)
        int half = idx / 73728;              // 0: A, 1: B
        int j = idx % 73728;
        int cc = j / 4608, e = j % 4608;
        int ci = e / 1152, t1 = e % 1152;
        int tap = t1 / 128, t2 = t1 % 128;
        int pair = t2 >> 2, s = t2 & 3;
        int co = pair*2 + (s & 1);
        const float* W;
        if (half == 0) W = (s < 2) ? Win : Waa;
        else           W = (s < 2) ? Wdn : Wbb;
        float v = W[(size_t)co*576 + (cc*4+ci)*9 + tap];
        if (half == 0) g_wA[j] = v; else g_wB[j] = v;
    } else if (idx < 221184) {               // g_wC1 / g_wC2 (conv layouts)
        int j = idx - 147456;
        int half = j / 36864;                // 0: conv1(Win), 1: conv2(Wdn)
        int k = j % 36864;
        int cg = k / 18432, r = k % 18432;
        int ci = r / 288, tap = (r % 288) / 32, co = r & 31;
        const float* W = half ? Wdn : Win;
        float v = W[(size_t)(cg*32+co)*576 + ci*9 + tap];
        if (half == 0) g_wC1[k] = v; else g_wC2[k] = v;
    }
}

// ============================================================
// conv1 + LIF scan A fused. cp.async double-buffered, 8 chunks of 8 ci.
// smem 16896 floats: s_in[2][6144] @0 | s_w[2][2304] @12288 ; transpose aliases
// Per thread: 2x2 px, 8 co (ty = {pg, cog}); staging ci = ty.
// ============================================================
__global__ __launch_bounds__(256, 3) void conv1_k(const float* __restrict__ u)
{
    extern __shared__ float sm[];          // 16896 floats

    int tid = threadIdx.x;
    int tx = tid & 31;
    int ty = tid >> 5;
    int pg  = ty >> 2;           // pixel column half (compute)
    int cog = ty & 3;            // co octet (compute)
    int tile = blockIdx.x;       // 0..127
    int cg = blockIdx.y;         // 0..1
    int b  = blockIdx.z;         // 0..15
    int h0 = (tile >> 3) * 2;
    int w0 = (tile & 7) * 4;

    const float* ubase = u + (size_t)(b*CC + ty) * HH*WW*TT;   // staging ci = ty
    const float* wcg = g_wC1 + (size_t)cg * 18432;
    bool tok = (tx < TT);
    int txc = tok ? tx : 0;

    unsigned long long acc[2][2][4];
    #pragma unroll
    for (int i = 0; i < 2; i++)
        #pragma unroll
        for (int j = 0; j < 2; j++)
            #pragma unroll
            for (int k = 0; k < 4; k++) acc[i][j][k] = 0ull;

    auto stage = [&](int cc, int buf) {
        float* si = sm + buf*6144;                 // [ci8][p24][t32]
        float* sw = sm + 12288 + buf*2304;
        const float* up = ubase + (size_t)cc * 8 * HH*WW*TT;
        #pragma unroll
        for (int p = 0; p < 24; p++) {
            int r = p / 6, c = p % 6;
            int gh = h0 - 1 + r, gw = w0 - 1 + c;
            bool ok = tok & (gh >= 0) & (gh < HH) & (gw >= 0) & (gw < WW);
            int ghc = min(max(gh, 0), HH-1);
            int gwc = min(max(gw, 0), WW-1);
            cpa4(smaddr(si + ty*768 + p*32 + tx),
                 up + ((size_t)ghc*WW + gwc)*TT + txc, ok);
        }
        #pragma unroll
        for (int k = 0; k < 3; k++) {
            int e = tid + k*256;
            if (e < 576)
                cpa16(smaddr(sw + e*4), wcg + (size_t)cc*2304 + e*4);
        }
        CP_COMMIT();
    };

    stage(0, 0);

    for (int cc = 0; cc < 8; cc++) {
        if (cc < 7) {
            stage(cc + 1, (cc + 1) & 1);
            asm volatile("cp.async.wait_group 1;" ::: "memory");
        } else {
            asm volatile("cp.async.wait_group 0;" ::: "memory");
        }
        __syncthreads();

        const float* s_ub = sm + (cc & 1)*6144;
        const float* s_wb = sm + 12288 + (cc & 1)*2304;

        #pragma unroll 2
        for (int ci = 0; ci < 8; ci++) {
            const float* su  = s_ub + ci*768 + (pg*2)*32 + tx;
            const float* swc = s_wb + ci*288 + cog*8;

            unsigned long long ra[4], rb[4];
            #pragma unroll
            for (int c = 0; c < 4; c++) ra[c] = pk2(su[0*192 + c*32]);
            #pragma unroll
            for (int c = 0; c < 4; c++) rb[c] = pk2(su[1*192 + c*32]);

            #pragma unroll
            for (int kh = 0; kh < 3; kh++) {
                ulonglong2 wv0[3], wv1[3];
                #pragma unroll
                for (int kw = 0; kw < 3; kw++) {
                    const float* wp = swc + (kh*3+kw)*32;
                    wv0[kw] = *(const ulonglong2*)wp;
                    wv1[kw] = *(const ulonglong2*)(wp + 4);
                }
                #pragma unroll
                for (int kw = 0; kw < 3; kw++)
                    #pragma unroll
                    for (int pcl = 0; pcl < 2; pcl++) {
                        unsigned long long va = ra[pcl+kw];
                        unsigned long long vb = rb[pcl+kw];
                        acc[0][pcl][0] = fma2(wv0[kw].x, va, acc[0][pcl][0]);
                        acc[0][pcl][1] = fma2(wv0[kw].y, va, acc[0][pcl][1]);
                        acc[0][pcl][2] = fma2(wv1[kw].x, va, acc[0][pcl][2]);
                        acc[0][pcl][3] = fma2(wv1[kw].y, va, acc[0][pcl][3]);
                        acc[1][pcl][0] = fma2(wv0[kw].x, vb, acc[1][pcl][0]);
                        acc[1][pcl][1] = fma2(wv0[kw].y, vb, acc[1][pcl][1]);
                        acc[1][pcl][2] = fma2(wv1[kw].x, vb, acc[1][pcl][2]);
                        acc[1][pcl][3] = fma2(wv1[kw].y, vb, acc[1][pcl][3]);
                    }
                if (kh < 2) {
                    #pragma unroll
                    for (int c = 0; c < 4; c++) {
                        ra[c] = rb[c];
                        rb[c] = pk2(su[(kh+2)*192 + c*32]);
                    }
                }
            }
        }
        __syncthreads();
    }

    // ---- transpose into [copix][t] pitch 33 (aliases whole smem) ----
    #pragma unroll
    for (int pr = 0; pr < 2; pr++)
        #pragma unroll
        for (int pcl = 0; pcl < 2; pcl++)
            #pragma unroll
            for (int k = 0; k < 4; k++) {
                float lo, hi;
                unpk2(acc[pr][pcl][k], lo, hi);
                int px = pr*4 + pg*2 + pcl;
                sm[((cog*8 + 2*k    )*8 + px)*33 + tx] = lo;
                sm[((cog*8 + 2*k + 1)*8 + px)*33 + tx] = hi;
            }
    __syncthreads();

    {
        int co_local = tid >> 3;
        int p = tid & 7;
        int h = h0 + (p >> 2);
        int w = w0 + (p & 3);
        int co = cg*32 + co_local;
        size_t pixIdx = ((size_t)(b*CC + co)*HH + h)*WW + w;

        float out[32];
        float v = 0.f, cnt = 0.f;
        #pragma unroll
        for (int t = 0; t < TT; t++) {
            v = 0.5f * v + sm[tid*33 + t];
            float sp = (v >= 1.0f) ? 1.0f : 0.0f;
            v -= sp;
            cnt += sp;
            out[t] = sp;
        }
        out[30] = 0.f; out[31] = 0.f;
        float4* op = (float4*)&g_sf[pixIdx * TP];
        #pragma unroll
        for (int i = 0; i < 8; i++)
            op[i] = make_float4(out[4*i], out[4*i+1], out[4*i+2], out[4*i+3]);
        g_za[pixIdx] = cnt * (1.0f / 30.0f);
    }
}

// ============================================================
// conv2 (stride-2 SAME: in = 2*out + k) + LIF scan B. cp.async pipeline.
// smem 13824 floats: s_in[2][5760] @0 | s_w[2][1152] @11520 ; transpose aliases
// __launch_bounds__(256,4): 4 blocks/SM (regs <= 64, smem 4x55296B fits)
// ============================================================
__global__ __launch_bounds__(256, 4) void conv2_k()
{
    extern __shared__ float sm[];          // 13824 floats

    int tid = threadIdx.x;
    int tx = tid & 31;
    int ty = tid >> 5;
    int pg  = ty >> 2;
    int cog = ty & 3;
    int lci = ty & 3;
    int rg  = ty >> 2;                // 0 -> rows 0..2, 1 -> rows 3..4
    int tile = blockIdx.x;            // 0..31
    int cg = blockIdx.y;
    int b  = blockIdx.z;
    int h0 = (tile >> 2) * 2;         // out coords
    int w0 = (tile & 3) * 4;

    const float* sfbase = g_sf + (size_t)(b*CC + lci) * HH*WW*TP;
    const float* wcg = g_wC2 + (size_t)cg * 18432;

    unsigned long long acc[2][2][4];
    #pragma unroll
    for (int i = 0; i < 2; i++)
        #pragma unroll
        for (int j = 0; j < 2; j++)
            #pragma unroll
            for (int k = 0; k < 4; k++) acc[i][j][k] = 0ull;

    auto stage = [&](int cc, int buf) {
        float* si = sm + buf*5760;               // [ci4][r5][c9][t32]
        float* sw = sm + 11520 + buf*1152;
        const float* up = sfbase + (size_t)cc * 4 * HH*WW*TP;
        #pragma unroll
        for (int rs = 0; rs < 3; rs++) {
            int r = rg*3 + rs;
            if (r < 5) {
                int gh = 2*h0 + r;
                bool hok = (gh < HH);
                int ghc = min(gh, HH-1);
                #pragma unroll
                for (int c = 0; c < 9; c++) {
                    int gw = 2*w0 + c;
                    bool ok = hok & (gw < WW);
                    int gwc = min(gw, WW-1);
                    cpa4(smaddr(si + lci*1440 + r*288 + c*32 + tx),
                         up + ((size_t)ghc*WW + gwc)*TP + tx, ok);
                }
            }
        }
        #pragma unroll
        for (int k = 0; k < 2; k++) {
            int e = tid + k*256;
            if (e < 288)
                cpa16(smaddr(sw + e*4), wcg + (size_t)cc*1152 + e*4);
        }
        CP_COMMIT();
    };

    stage(0, 0);

    for (int cc = 0; cc < 16; cc++) {
        if (cc < 15) {
            stage(cc + 1, (cc + 1) & 1);
            asm volatile("cp.async.wait_group 1;" ::: "memory");
        } else {
            asm volatile("cp.async.wait_group 0;" ::: "memory");
        }
        __syncthreads();

        const float* s_ub = sm + (cc & 1)*5760;
        const float* s_wb = sm + 11520 + (cc & 1)*1152;

        #pragma unroll
        for (int ci = 0; ci < 4; ci++) {
            const float* su  = s_ub + ci*1440 + (pg*4)*32 + tx;
            const float* swc = s_wb + ci*288 + cog*8;

            #pragma unroll
            for (int kh = 0; kh < 3; kh++) {
                ulonglong2 wv0[3], wv1[3];
                #pragma unroll
                for (int kw = 0; kw < 3; kw++) {
                    const float* wp = swc + (kh*3+kw)*32;
                    wv0[kw] = *(const ulonglong2*)wp;
                    wv1[kw] = *(const ulonglong2*)(wp + 4);
                }
                #pragma unroll
                for (int pr = 0; pr < 2; pr++) {
                    int r = 2*pr + kh;
                    unsigned long long vd[5];
                    #pragma unroll
                    for (int c = 0; c < 5; c++)
                        vd[c] = pk2(su[r*288 + c*32]);
                    #pragma unroll
                    for (int kw = 0; kw < 3; kw++)
                        #pragma unroll
                        for (int pcl = 0; pcl < 2; pcl++) {
                            unsigned long long v = vd[2*pcl + kw];
                            acc[pr][pcl][0] = fma2(wv0[kw].x, v, acc[pr][pcl][0]);
                            acc[pr][pcl][1] = fma2(wv0[kw].y, v, acc[pr][pcl][1]);
                            acc[pr][pcl][2] = fma2(wv1[kw].x, v, acc[pr][pcl][2]);
                            acc[pr][pcl][3] = fma2(wv1[kw].y, v, acc[pr][pcl][3]);
                        }
                }
            }
        }
        __syncthreads();
    }

    // ---- transpose (aliases smem) + scan B ----
    #pragma unroll
    for (int pr = 0; pr < 2; pr++)
        #pragma unroll
        for (int pcl = 0; pcl < 2; pcl++)
            #pragma unroll
            for (int k = 0; k < 4; k++) {
                float lo, hi;
                unpk2(acc[pr][pcl][k], lo, hi);
                int px = pr*4 + pg*2 + pcl;
                sm[((cog*8 + 2*k    )*8 + px)*33 + tx] = lo;
                sm[((cog*8 + 2*k + 1)*8 + px)*33 + tx] = hi;
            }
    __syncthreads();
    {
        int co_local = tid >> 3;
        int p = tid & 7;
        int h = h0 + (p >> 2);
        int w = w0 + (p & 3);
        int co = cg*32 + co_local;
        float v = 0.f, cnt = 0.f;
        #pragma unroll
        for (int t = 0; t < TT; t++) {
            v = 0.5f * v + sm[tid*33 + t];
            float sp = (v >= 1.0f) ? 1.0f : 0.0f;
            v -= sp;
            cnt += sp;
        }
        g_zb[((size_t)(b*CC + co)*HO + h)*WO + w] = cnt * (1.0f / 30.0f);
    }
}

// ============================================================
// u_bar: leaky temporal average. Thread owns 2 adjacent pixels:
// 240B = 15 LDG.128 (aligned). Per-pixel arithmetic unchanged.
// ============================================================
__global__ __launch_bounds__(256) void ubar_k(const float* __restrict__ u)
{
    int pp = blockIdx.x * blockDim.x + threadIdx.x;
    if (pp >= BB*CC*HH*WW/2) return;
    const float4* up4 = (const float4*)(u + (size_t)pp * 60);
    float uu[60];
    #pragma unroll
    for (int i = 0; i < 15; i++) {
        float4 v = up4[i];
        uu[4*i] = v.x; uu[4*i+1] = v.y; uu[4*i+2] = v.z; uu[4*i+3] = v.w;
    }
    float p = 1.0f;
    #pragma unroll
    for (int i = 0; i < 30; i++) p *= 0.9f;      // 0.9^30
    float p31 = p * 0.9f;
    float inv = 0.1f / (1.0f - p31);
    #pragma unroll
    for (int s = 0; s < 2; s++) {
        const float* x = uu + s*30;
        float acc = (1.0f + p) * x[29];
        float w = 0.9f;
        #pragma unroll
        for (int j = 28; j >= 0; j--) {
            acc += w * x[j];
            w *= 0.9f;
        }
        g_ubar[2*pp + s] = acc * inv;
    }
}

// ============================================================
// final A: a = clip(conv(u_bar,W_in) + conv(z_a,W_aa), 0, 1)
// 512 blocks: 32 tiles (4x8 px) x 16 b. thread: pair=tid&31 (2 co), pb=tid>>5 (2x2 px)
// ============================================================
__global__ __launch_bounds__(256) void finalA_k(float* __restrict__ outA)
{
    __shared__ __align__(16) float s_ubv[240];     // [4ci][6][10]
    __shared__ __align__(16) float s_zav[240];
    __shared__ __align__(16) float s_wv[4608];     // [4ci][9tap][32pair][4]

    int tid = threadIdx.x;
    int pairI = tid & 31;
    int pb = tid >> 5;               // 0..7
    int pr0 = (pb >> 2) * 2;         // 0 or 2
    int pc0 = (pb & 3) * 2;          // 0,2,4,6
    int tile = blockIdx.x;           // 0..31
    int b    = blockIdx.z;
    int h0 = (tile >> 2) * 4, w0 = (tile & 3) * 8;

    unsigned long long acc[2][2];
    #pragma unroll
    for (int i = 0; i < 2; i++)
        #pragma unroll
        for (int j = 0; j < 2; j++) acc[i][j] = 0ull;

    float2 pw[9];
    float  pv[2];

    auto ld_w = [&](int cc) {
        const float2* src = (const float2*)g_wA + (size_t)cc*2304 + tid;
        #pragma unroll
        for (int k = 0; k < 9; k++) pw[k] = src[k*256];
    };
    auto ld_v = [&](int cc) {
        #pragma unroll
        for (int k = 0; k < 2; k++) {
            int e = tid + k*256;
            float v = 0.f;
            if (e < 480) {
                int a = (e >= 240);
                int i = e - a*240;
                int ci = i / 60; int rem = i % 60;
                int r = rem / 10, c = rem % 10;
                int gh = h0 - 1 + r, gw = w0 - 1 + c;
                if (gh >= 0 && gh < HH && gw >= 0 && gw < WW) {
                    size_t gi = ((size_t)(b*CC + cc*4+ci)*HH + gh)*WW + gw;
                    v = a ? g_za[gi] : g_ubar[gi];
                }
            }
            pv[k] = v;
        }
    };

    ld_w(0); ld_v(0);

    for (int cc = 0; cc < 16; cc++) {
        {
            float2* wd = (float2*)s_wv + tid;
            #pragma unroll
            for (int k = 0; k < 9; k++) wd[k*256] = pw[k];
            #pragma unroll
            for (int k = 0; k < 2; k++) {
                int e = tid + k*256;
                if (e < 480) {
                    if (e >= 240) s_zav[e-240] = pv[k];
                    else          s_ubv[e]     = pv[k];
                }
            }
        }
        __syncthreads();
        if (cc < 15) { ld_w(cc+1); ld_v(cc+1); }

        #pragma unroll 2
        for (int ci = 0; ci < 4; ci++) {
            unsigned long long ua[4], ub[4], za[4], zb[4];
            #pragma unroll
            for (int c = 0; c < 4; c++) {
                ua[c] = pk2(s_ubv[ci*60 + (pr0  )*10 + pc0 + c]);
                za[c] = pk2(s_zav[ci*60 + (pr0  )*10 + pc0 + c]);
                ub[c] = pk2(s_ubv[ci*60 + (pr0+1)*10 + pc0 + c]);
                zb[c] = pk2(s_zav[ci*60 + (pr0+1)*10 + pc0 + c]);
            }
            #pragma unroll
            for (int kh = 0; kh < 3; kh++) {
                ulonglong2 wv[3];
                #pragma unroll
                for (int kw = 0; kw < 3; kw++)
                    wv[kw] = *(const ulonglong2*)(s_wv + ((ci*9 + kh*3+kw)*32 + pairI)*4);
                #pragma unroll
                for (int kw = 0; kw < 3; kw++)
                    #pragma unroll
                    for (int px = 0; px < 2; px++) {
                        acc[0][px] = fma2(wv[kw].x, ua[px+kw], acc[0][px]);
                        acc[0][px] = fma2(wv[kw].y, za[px+kw], acc[0][px]);
                        acc[1][px] = fma2(wv[kw].x, ub[px+kw], acc[1][px]);
                        acc[1][px] = fma2(wv[kw].y, zb[px+kw], acc[1][px]);
                    }
                if (kh < 2) {
                    #pragma unroll
                    for (int c = 0; c < 4; c++) {
                        ua[c] = ub[c]; za[c] = zb[c];
                        ub[c] = pk2(s_ubv[ci*60 + (pr0+kh+2)*10 + pc0 + c]);
                        zb[c] = pk2(s_zav[ci*60 + (pr0+kh+2)*10 + pc0 + c]);
                    }
                }
            }
        }
        __syncthreads();
    }

    int co0 = 2 * pairI;
    #pragma unroll
    for (int pr = 0; pr < 2; pr++)
        #pragma unroll
        for (int px = 0; px < 2; px++) {
            int h = h0 + pr0 + pr;
            int w = w0 + pc0 + px;
            float lo, hi;
            unpk2(acc[pr][px], lo, hi);
            outA[((b*CC + co0    )*HH + h)*WW + w] = fminf(fmaxf(lo, 0.f), 1.f);
            outA[((b*CC + co0 + 1)*HH + h)*WW + w] = fminf(fmaxf(hi, 0.f), 1.f);
        }
}

// ============================================================
// final B: b_out = clip(conv(a,W_down,s2) + conv(z_b,W_bb), 0, 1) on 16x16
// 128 blocks: 8 tiles (4x8 out-px) x 16 b. thread: pair=tid&31 (2 co), 2x2 px.
// ============================================================
__global__ __launch_bounds__(256) void finalB_k(const float* __restrict__ aIn,
                                                float* __restrict__ outB)
{
    __shared__ __align__(16) float s_av[612];      // [4ci][9][17] (in region @ 2h0,2w0)
    __shared__ __align__(16) float s_zv[240];      // [4ci][6][10] (halo 1 @ h0-1,w0-1)
    __shared__ __align__(16) float s_wv[4608];     // [4ci][9tap][32pair][4]

    int tid = threadIdx.x;
    int pairI = tid & 31;
    int pb = tid >> 5;               // 0..7
    int pr0 = (pb >> 2) * 2;         // 0 or 2
    int pc0 = (pb & 3) * 2;          // 0,2,4,6
    int tile = blockIdx.x;           // 0..7
    int b    = blockIdx.z;
    int h0 = (tile >> 1) * 4, w0 = (tile & 1) * 8;   // out coords

    unsigned long long acc[2][2];
    #pragma unroll
    for (int i = 0; i < 2; i++)
        #pragma unroll
        for (int j = 0; j < 2; j++) acc[i][j] = 0ull;

    float2 pw[9];
    float  pv[4];

    auto ld_w = [&](int cc) {
        const float2* src = (const float2*)g_wB + (size_t)cc*2304 + tid;
        #pragma unroll
        for (int k = 0; k < 9; k++) pw[k] = src[k*256];
    };
    auto ld_v = [&](int cc) {
        #pragma unroll
        for (int k = 0; k < 4; k++) {
            int e = tid + k*256;
            float v = 0.f;
            if (e < 612) {                       // a tile
                int ci = e / 153; int i = e % 153;
                int r = i / 17, c = i % 17;
                int gh = 2*h0 + r, gw = 2*w0 + c;
                if (gh < HH && gw < WW)
                    v = aIn[((size_t)(b*CC + cc*4+ci)*HH + gh)*WW + gw];
            } else if (e < 852) {                // z tile
                int ez = e - 612;
                int ci = ez / 60; int i = ez % 60;
                int r = i / 10, c = i % 10;
                int gh = h0 - 1 + r, gw = w0 - 1 + c;
                if (gh >= 0 && gh < HO && gw >= 0 && gw < WO)
                    v = g_zb[((size_t)(b*CC + cc*4+ci)*HO + gh)*WO + gw];
            }
            pv[k] = v;
        }
    };

    ld_w(0); ld_v(0);

    for (int cc = 0; cc < 16; cc++) {
        {
            float2* wd = (float2*)s_wv + tid;
            #pragma unroll
            for (int k = 0; k < 9; k++) wd[k*256] = pw[k];
            #pragma unroll
            for (int k = 0; k < 4; k++) {
                int e = tid + k*256;
                if (e < 612)      s_av[e]     = pv[k];
                else if (e < 852) s_zv[e-612] = pv[k];
            }
        }
        __syncthreads();
        if (cc < 15) { ld_w(cc+1); ld_v(cc+1); }

        #pragma unroll 2
        for (int ci = 0; ci < 4; ci++) {
            #pragma unroll
            for (int kh = 0; kh < 3; kh++) {
                ulonglong2 wv[3];
                #pragma unroll
                for (int kw = 0; kw < 3; kw++)
                    wv[kw] = *(const ulonglong2*)(s_wv + ((ci*9 + kh*3+kw)*32 + pairI)*4);
                #pragma unroll
                for (int pr = 0; pr < 2; pr++) {
                    int ra = 2*(pr0 + pr) + kh;      // 0..8
                    int rz = pr0 + pr + kh;          // 0..5
                    unsigned long long va[5], vz[4];
                    #pragma unroll
                    for (int c = 0; c < 5; c++)
                        va[c] = pk2(s_av[ci*153 + ra*17 + 2*pc0 + c]);
                    #pragma unroll
                    for (int c = 0; c < 4; c++)
                        vz[c] = pk2(s_zv[ci*60 + rz*10 + pc0 + c]);
                    #pragma unroll
                    for (int kw = 0; kw < 3; kw++)
                        #pragma unroll
                        for (int px = 0; px < 2; px++) {
                            acc[pr][px] = fma2(wv[kw].x, va[2*px+kw], acc[pr][px]);
                            acc[pr][px] = fma2(wv[kw].y, vz[px+kw],   acc[pr][px]);
                        }
                }
            }
        }
        __syncthreads();
    }

    int co0 = 2 * pairI;
    #pragma unroll
    for (int pr = 0; pr < 2; pr++)
        #pragma unroll
        for (int px = 0; px < 2; px++) {
            int h = h0 + pr0 + pr;
            int w = w0 + pc0 + px;
            float lo, hi;
            unpk2(acc[pr][px], lo, hi);
            outB[((b*CC + co0    )*HO + h)*WO + w] = fminf(fmaxf(lo, 0.f), 1.f);
            outB[((b*CC + co0 + 1)*HO + h)*WO + w] = fminf(fmaxf(hi, 0.f), 1.f);
        }
}

// ============================================================
extern "C" void kernel_launch(void* const* d_in, const int* in_sizes, int n_in,
                              void* d_out, int out_size)
{
    (void)in_sizes; (void)n_in; (void)out_size;
    const float* u   = (const float*)d_in[0];
    const float* Win = (const float*)d_in[1];
    const float* Waa = (const float*)d_in[2];
    const float* Wdn = (const float*)d_in[3];
    const float* Wbb = (const float*)d_in[4];
    float* outA = (float*)d_out;                      // a: [16,64,32,32]
    float* outB = outA + BB*CC*HH*WW;                 // b: [16,64,16,16]

    cudaFuncSetAttribute(conv1_k, cudaFuncAttributeMaxDynamicSharedMemorySize, 67584);
    cudaFuncSetAttribute(conv2_k, cudaFuncAttributeMaxDynamicSharedMemorySize, 55296);

    wprep_k<<<864, 256>>>(Win, Waa, Wdn, Wbb);
    ubar_k <<<(BB*CC*HH*WW/2 + 255)/256, 256>>>(u);
    conv1_k<<<dim3(128, 2, BB), 256, 67584>>>(u);
    conv2_k<<<dim3(32, 2, BB), 256, 55296>>>();
    finalA_k<<<dim3(32, 1, BB), 256>>>(outA);
    finalB_k<<<dim3(8, 1, BB), 256>>>(outA, outB);
}

// round 16
// speedup vs baseline: 1.0125x; 1.0125x over previous
#include <cuda_runtime.h>
#include <cstdint>

#define BB 16
#define CC 64
#define HH 32
#define WW 32
#define TT 30
#define TP 32
#define HO 16
#define WO 16

// ---- scratch (static device memory; no allocations) ----
__device__ float g_sf[BB*CC*HH*WW*TP];   // spikes s_a as float (t padded to 32)
__device__ float g_za[BB*CC*HH*WW];
__device__ float g_zb[BB*CC*HO*WO];
__device__ float g_ubar[BB*CC*HH*WW];

// pre-interleaved weights
__device__ __align__(16) float g_wA [16*4608];   // finalA: [cc][ci4][tap9][pair32][4]
__device__ __align__(16) float g_wB [16*4608];   // finalB: same layout (Wdn/Wbb)
__device__ __align__(16) float g_wC1[2*18432];   // conv1:  [cg][(ci*9+tap)*32+co]
__device__ __align__(16) float g_wC2[2*18432];   // conv2:  same (Wdn)

// packed f32x2 helpers
static __device__ __forceinline__ unsigned long long pk2(float x) {
    unsigned long long r;
    asm("mov.b64 %0, {%1, %1};" : "=l"(r) : "f"(x));
    return r;
}
static __device__ __forceinline__ unsigned long long fma2(unsigned long long a,
                                                          unsigned long long b,
                                                          unsigned long long c) {
    unsigned long long d;
    asm("fma.rn.f32x2 %0, %1, %2, %3;" : "=l"(d) : "l"(a), "l"(b), "l"(c));
    return d;
}
static __device__ __forceinline__ void unpk2(unsigned long long v, float& lo, float& hi) {
    asm("mov.b64 {%0, %1}, %2;" : "=f"(lo), "=f"(hi) : "l"(v));
}

// cp.async helpers
static __device__ __forceinline__ void cpa4(unsigned int dst, const void* src, bool ok) {
    asm volatile("cp.async.ca.shared.global [%0], [%1], 4, %2;"
                 :: "r"(dst), "l"(src), "r"(ok ? 4u : 0u));
}
static __device__ __forceinline__ void cpa16(unsigned int dst, const void* src) {
    asm volatile("cp.async.cg.shared.global [%0], [%1], 16;" :: "r"(dst), "l"(src));
}
static __device__ __forceinline__ unsigned int smaddr(const void* p) {
    return (unsigned int)__cvta_generic_to_shared(p);
}
#define CP_COMMIT() asm volatile("cp.async.commit_group;" ::: "memory")

// ============================================================
// weight prep: scatter-read once, so every consumer does coalesced loads
// ============================================================
__global__ __launch_bounds__(256) void wprep_k(const float* __restrict__ Win,
                                               const float* __restrict__ Waa,
                                               const float* __restrict__ Wdn,
                                               const float* __restrict__ Wbb)
{
    int idx = blockIdx.x * 256 + threadIdx.x;
    if (idx < 147456) {                      // g_wA / g_wB (pair-interleaved)
        int half = idx / 73728;              // 0: A, 1: B
        int j = idx % 73728;
        int cc = j / 4608, e = j % 4608;
        int ci = e / 1152, t1 = e % 1152;
        int tap = t1 / 128, t2 = t1 % 128;
        int pair = t2 >> 2, s = t2 & 3;
        int co = pair*2 + (s & 1);
        const float* W;
        if (half == 0) W = (s < 2) ? Win : Waa;
        else           W = (s < 2) ? Wdn : Wbb;
        float v = W[(size_t)co*576 + (cc*4+ci)*9 + tap];
        if (half == 0) g_wA[j] = v; else g_wB[j] = v;
    } else if (idx < 221184) {               // g_wC1 / g_wC2 (conv layouts)
        int j = idx - 147456;
        int half = j / 36864;                // 0: conv1(Win), 1: conv2(Wdn)
        int k = j % 36864;
        int cg = k / 18432, r = k % 18432;
        int ci = r / 288, tap = (r % 288) / 32, co = r & 31;
        const float* W = half ? Wdn : Win;
        float v = W[(size_t)(cg*32+co)*576 + ci*9 + tap];
        if (half == 0) g_wC1[k] = v; else g_wC2[k] = v;
    }
}

// ============================================================
// conv1 + LIF scan A fused. cp.async double-buffered, 8 chunks of 8 ci.
// smem 16896 floats: s_in[2][6144] @0 | s_w[2][2304] @12288 ; transpose aliases
// Per thread: 2x2 px, 8 co (ty = {pg, cog}); staging ci = ty.
// ============================================================
__global__ __launch_bounds__(256, 3) void conv1_k(const float* __restrict__ u)
{
    extern __shared__ float sm[];          // 16896 floats

    int tid = threadIdx.x;
    int tx = tid & 31;
    int ty = tid >> 5;
    int pg  = ty >> 2;           // pixel column half (compute)
    int cog = ty & 3;            // co octet (compute)
    int tile = blockIdx.x;       // 0..127
    int cg = blockIdx.y;         // 0..1
    int b  = blockIdx.z;         // 0..15
    int h0 = (tile >> 3) * 2;
    int w0 = (tile & 7) * 4;

    const float* ubase = u + (size_t)(b*CC + ty) * HH*WW*TT;   // staging ci = ty
    const float* wcg = g_wC1 + (size_t)cg * 18432;
    bool tok = (tx < TT);
    int txc = tok ? tx : 0;

    unsigned long long acc[2][2][4];
    #pragma unroll
    for (int i = 0; i < 2; i++)
        #pragma unroll
        for (int j = 0; j < 2; j++)
            #pragma unroll
            for (int k = 0; k < 4; k++) acc[i][j][k] = 0ull;

    auto stage = [&](int cc, int buf) {
        float* si = sm + buf*6144;                 // [ci8][p24][t32]
        float* sw = sm + 12288 + buf*2304;
        const float* up = ubase + (size_t)cc * 8 * HH*WW*TT;
        #pragma unroll
        for (int p = 0; p < 24; p++) {
            int r = p / 6, c = p % 6;
            int gh = h0 - 1 + r, gw = w0 - 1 + c;
            bool ok = tok & (gh >= 0) & (gh < HH) & (gw >= 0) & (gw < WW);
            int ghc = min(max(gh, 0), HH-1);
            int gwc = min(max(gw, 0), WW-1);
            cpa4(smaddr(si + ty*768 + p*32 + tx),
                 up + ((size_t)ghc*WW + gwc)*TT + txc, ok);
        }
        #pragma unroll
        for (int k = 0; k < 3; k++) {
            int e = tid + k*256;
            if (e < 576)
                cpa16(smaddr(sw + e*4), wcg + (size_t)cc*2304 + e*4);
        }
        CP_COMMIT();
    };

    stage(0, 0);

    for (int cc = 0; cc < 8; cc++) {
        if (cc < 7) {
            stage(cc + 1, (cc + 1) & 1);
            asm volatile("cp.async.wait_group 1;" ::: "memory");
        } else {
            asm volatile("cp.async.wait_group 0;" ::: "memory");
        }
        __syncthreads();

        const float* s_ub = sm + (cc & 1)*6144;
        const float* s_wb = sm + 12288 + (cc & 1)*2304;

        #pragma unroll 2
        for (int ci = 0; ci < 8; ci++) {
            const float* su  = s_ub + ci*768 + (pg*2)*32 + tx;
            const float* swc = s_wb + ci*288 + cog*8;

            unsigned long long ra[4], rb[4];
            #pragma unroll
            for (int c = 0; c < 4; c++) ra[c] = pk2(su[0*192 + c*32]);
            #pragma unroll
            for (int c = 0; c < 4; c++) rb[c] = pk2(su[1*192 + c*32]);

            #pragma unroll
            for (int kh = 0; kh < 3; kh++) {
                ulonglong2 wv0[3], wv1[3];
                #pragma unroll
                for (int kw = 0; kw < 3; kw++) {
                    const float* wp = swc + (kh*3+kw)*32;
                    wv0[kw] = *(const ulonglong2*)wp;
                    wv1[kw] = *(const ulonglong2*)(wp + 4);
                }
                #pragma unroll
                for (int kw = 0; kw < 3; kw++)
                    #pragma unroll
                    for (int pcl = 0; pcl < 2; pcl++) {
                        unsigned long long va = ra[pcl+kw];
                        unsigned long long vb = rb[pcl+kw];
                        acc[0][pcl][0] = fma2(wv0[kw].x, va, acc[0][pcl][0]);
                        acc[0][pcl][1] = fma2(wv0[kw].y, va, acc[0][pcl][1]);
                        acc[0][pcl][2] = fma2(wv1[kw].x, va, acc[0][pcl][2]);
                        acc[0][pcl][3] = fma2(wv1[kw].y, va, acc[0][pcl][3]);
                        acc[1][pcl][0] = fma2(wv0[kw].x, vb, acc[1][pcl][0]);
                        acc[1][pcl][1] = fma2(wv0[kw].y, vb, acc[1][pcl][1]);
                        acc[1][pcl][2] = fma2(wv1[kw].x, vb, acc[1][pcl][2]);
                        acc[1][pcl][3] = fma2(wv1[kw].y, vb, acc[1][pcl][3]);
                    }
                if (kh < 2) {
                    #pragma unroll
                    for (int c = 0; c < 4; c++) {
                        ra[c] = rb[c];
                        rb[c] = pk2(su[(kh+2)*192 + c*32]);
                    }
                }
            }
        }
        __syncthreads();
    }

    // ---- transpose into [copix][t] pitch 33 (aliases whole smem) ----
    #pragma unroll
    for (int pr = 0; pr < 2; pr++)
        #pragma unroll
        for (int pcl = 0; pcl < 2; pcl++)
            #pragma unroll
            for (int k = 0; k < 4; k++) {
                float lo, hi;
                unpk2(acc[pr][pcl][k], lo, hi);
                int px = pr*4 + pg*2 + pcl;
                sm[((cog*8 + 2*k    )*8 + px)*33 + tx] = lo;
                sm[((cog*8 + 2*k + 1)*8 + px)*33 + tx] = hi;
            }
    __syncthreads();

    {
        int co_local = tid >> 3;
        int p = tid & 7;
        int h = h0 + (p >> 2);
        int w = w0 + (p & 3);
        int co = cg*32 + co_local;
        size_t pixIdx = ((size_t)(b*CC + co)*HH + h)*WW + w;

        float out[32];
        float v = 0.f, cnt = 0.f;
        #pragma unroll
        for (int t = 0; t < TT; t++) {
            v = 0.5f * v + sm[tid*33 + t];
            float sp = (v >= 1.0f) ? 1.0f : 0.0f;
            v -= sp;
            cnt += sp;
            out[t] = sp;
        }
        out[30] = 0.f; out[31] = 0.f;
        float4* op = (float4*)&g_sf[pixIdx * TP];
        #pragma unroll
        for (int i = 0; i < 8; i++)
            op[i] = make_float4(out[4*i], out[4*i+1], out[4*i+2], out[4*i+3]);
        g_za[pixIdx] = cnt * (1.0f / 30.0f);
    }
}

// ============================================================
// conv2 (stride-2 SAME: in = 2*out + k) + LIF scan B. cp.async pipeline.
// smem 13824 floats: s_in[2][5760] @0 | s_w[2][1152] @11520 ; transpose aliases
// (256,3): regs ~80, no spills — (256,4) measured as a spill regression in R15.
// ============================================================
__global__ __launch_bounds__(256, 3) void conv2_k()
{
    extern __shared__ float sm[];          // 13824 floats

    int tid = threadIdx.x;
    int tx = tid & 31;
    int ty = tid >> 5;
    int pg  = ty >> 2;
    int cog = ty & 3;
    int lci = ty & 3;
    int rg  = ty >> 2;                // 0 -> rows 0..2, 1 -> rows 3..4
    int tile = blockIdx.x;            // 0..31
    int cg = blockIdx.y;
    int b  = blockIdx.z;
    int h0 = (tile >> 2) * 2;         // out coords
    int w0 = (tile & 3) * 4;

    const float* sfbase = g_sf + (size_t)(b*CC + lci) * HH*WW*TP;
    const float* wcg = g_wC2 + (size_t)cg * 18432;

    unsigned long long acc[2][2][4];
    #pragma unroll
    for (int i = 0; i < 2; i++)
        #pragma unroll
        for (int j = 0; j < 2; j++)
            #pragma unroll
            for (int k = 0; k < 4; k++) acc[i][j][k] = 0ull;

    auto stage = [&](int cc, int buf) {
        float* si = sm + buf*5760;               // [ci4][r5][c9][t32]
        float* sw = sm + 11520 + buf*1152;
        const float* up = sfbase + (size_t)cc * 4 * HH*WW*TP;
        #pragma unroll
        for (int rs = 0; rs < 3; rs++) {
            int r = rg*3 + rs;
            if (r < 5) {
                int gh = 2*h0 + r;
                bool hok = (gh < HH);
                int ghc = min(gh, HH-1);
                #pragma unroll
                for (int c = 0; c < 9; c++) {
                    int gw = 2*w0 + c;
                    bool ok = hok & (gw < WW);
                    int gwc = min(gw, WW-1);
                    cpa4(smaddr(si + lci*1440 + r*288 + c*32 + tx),
                         up + ((size_t)ghc*WW + gwc)*TP + tx, ok);
                }
            }
        }
        #pragma unroll
        for (int k = 0; k < 2; k++) {
            int e = tid + k*256;
            if (e < 288)
                cpa16(smaddr(sw + e*4), wcg + (size_t)cc*1152 + e*4);
        }
        CP_COMMIT();
    };

    stage(0, 0);

    for (int cc = 0; cc < 16; cc++) {
        if (cc < 15) {
            stage(cc + 1, (cc + 1) & 1);
            asm volatile("cp.async.wait_group 1;" ::: "memory");
        } else {
            asm volatile("cp.async.wait_group 0;" ::: "memory");
        }
        __syncthreads();

        const float* s_ub = sm + (cc & 1)*5760;
        const float* s_wb = sm + 11520 + (cc & 1)*1152;

        #pragma unroll
        for (int ci = 0; ci < 4; ci++) {
            const float* su  = s_ub + ci*1440 + (pg*4)*32 + tx;
            const float* swc = s_wb + ci*288 + cog*8;

            #pragma unroll
            for (int kh = 0; kh < 3; kh++) {
                ulonglong2 wv0[3], wv1[3];
                #pragma unroll
                for (int kw = 0; kw < 3; kw++) {
                    const float* wp = swc + (kh*3+kw)*32;
                    wv0[kw] = *(const ulonglong2*)wp;
                    wv1[kw] = *(const ulonglong2*)(wp + 4);
                }
                #pragma unroll
                for (int pr = 0; pr < 2; pr++) {
                    int r = 2*pr + kh;
                    unsigned long long vd[5];
                    #pragma unroll
                    for (int c = 0; c < 5; c++)
                        vd[c] = pk2(su[r*288 + c*32]);
                    #pragma unroll
                    for (int kw = 0; kw < 3; kw++)
                        #pragma unroll
                        for (int pcl = 0; pcl < 2; pcl++) {
                            unsigned long long v = vd[2*pcl + kw];
                            acc[pr][pcl][0] = fma2(wv0[kw].x, v, acc[pr][pcl][0]);
                            acc[pr][pcl][1] = fma2(wv0[kw].y, v, acc[pr][pcl][1]);
                            acc[pr][pcl][2] = fma2(wv1[kw].x, v, acc[pr][pcl][2]);
                            acc[pr][pcl][3] = fma2(wv1[kw].y, v, acc[pr][pcl][3]);
                        }
                }
            }
        }
        __syncthreads();
    }

    // ---- transpose (aliases smem) + scan B ----
    #pragma unroll
    for (int pr = 0; pr < 2; pr++)
        #pragma unroll
        for (int pcl = 0; pcl < 2; pcl++)
            #pragma unroll
            for (int k = 0; k < 4; k++) {
                float lo, hi;
                unpk2(acc[pr][pcl][k], lo, hi);
                int px = pr*4 + pg*2 + pcl;
                sm[((cog*8 + 2*k    )*8 + px)*33 + tx] = lo;
                sm[((cog*8 + 2*k + 1)*8 + px)*33 + tx] = hi;
            }
    __syncthreads();
    {
        int co_local = tid >> 3;
        int p = tid & 7;
        int h = h0 + (p >> 2);
        int w = w0 + (p & 3);
        int co = cg*32 + co_local;
        float v = 0.f, cnt = 0.f;
        #pragma unroll
        for (int t = 0; t < TT; t++) {
            v = 0.5f * v + sm[tid*33 + t];
            float sp = (v >= 1.0f) ? 1.0f : 0.0f;
            v -= sp;
            cnt += sp;
        }
        g_zb[((size_t)(b*CC + co)*HO + h)*WO + w] = cnt * (1.0f / 30.0f);
    }
}

// ============================================================
// u_bar: leaky temporal average (float2 loads — R13 form)
// ============================================================
__global__ __launch_bounds__(256) void ubar_k(const float* __restrict__ u)
{
    int pix = blockIdx.x * blockDim.x + threadIdx.x;
    if (pix >= BB*CC*HH*WW) return;
    const float2* up2 = (const float2*)(u + (size_t)pix * TT);
    float uu[30];
    #pragma unroll
    for (int i = 0; i < 15; i++) {
        float2 v = up2[i];
        uu[2*i] = v.x; uu[2*i+1] = v.y;
    }
    float p = 1.0f;
    #pragma unroll
    for (int i = 0; i < 30; i++) p *= 0.9f;      // 0.9^30
    float p31 = p * 0.9f;
    float inv = 0.1f / (1.0f - p31);
    float acc = (1.0f + p) * uu[29];
    float w = 0.9f;
    #pragma unroll
    for (int j = 28; j >= 0; j--) {
        acc += w * uu[j];
        w *= 0.9f;
    }
    g_ubar[pix] = acc * inv;
}

// ============================================================
// final A: a = clip(conv(u_bar,W_in) + conv(z_a,W_aa), 0, 1)
// 512 blocks: 32 tiles (4x8 px) x 16 b. thread: pair=tid&31 (2 co), pb=tid>>5 (2x2 px)
// ============================================================
__global__ __launch_bounds__(256) void finalA_k(float* __restrict__ outA)
{
    __shared__ __align__(16) float s_ubv[240];     // [4ci][6][10]
    __shared__ __align__(16) float s_zav[240];
    __shared__ __align__(16) float s_wv[4608];     // [4ci][9tap][32pair][4]

    int tid = threadIdx.x;
    int pairI = tid & 31;
    int pb = tid >> 5;               // 0..7
    int pr0 = (pb >> 2) * 2;         // 0 or 2
    int pc0 = (pb & 3) * 2;          // 0,2,4,6
    int tile = blockIdx.x;           // 0..31
    int b    = blockIdx.z;
    int h0 = (tile >> 2) * 4, w0 = (tile & 3) * 8;

    unsigned long long acc[2][2];
    #pragma unroll
    for (int i = 0; i < 2; i++)
        #pragma unroll
        for (int j = 0; j < 2; j++) acc[i][j] = 0ull;

    float2 pw[9];
    float  pv[2];

    auto ld_w = [&](int cc) {
        const float2* src = (const float2*)g_wA + (size_t)cc*2304 + tid;
        #pragma unroll
        for (int k = 0; k < 9; k++) pw[k] = src[k*256];
    };
    auto ld_v = [&](int cc) {
        #pragma unroll
        for (int k = 0; k < 2; k++) {
            int e = tid + k*256;
            float v = 0.f;
            if (e < 480) {
                int a = (e >= 240);
                int i = e - a*240;
                int ci = i / 60; int rem = i % 60;
                int r = rem / 10, c = rem % 10;
                int gh = h0 - 1 + r, gw = w0 - 1 + c;
                if (gh >= 0 && gh < HH && gw >= 0 && gw < WW) {
                    size_t gi = ((size_t)(b*CC + cc*4+ci)*HH + gh)*WW + gw;
                    v = a ? g_za[gi] : g_ubar[gi];
                }
            }
            pv[k] = v;
        }
    };

    ld_w(0); ld_v(0);

    for (int cc = 0; cc < 16; cc++) {
        {
            float2* wd = (float2*)s_wv + tid;
            #pragma unroll
            for (int k = 0; k < 9; k++) wd[k*256] = pw[k];
            #pragma unroll
            for (int k = 0; k < 2; k++) {
                int e = tid + k*256;
                if (e < 480) {
                    if (e >= 240) s_zav[e-240] = pv[k];
                    else          s_ubv[e]     = pv[k];
                }
            }
        }
        __syncthreads();
        if (cc < 15) { ld_w(cc+1); ld_v(cc+1); }

        #pragma unroll 2
        for (int ci = 0; ci < 4; ci++) {
            unsigned long long ua[4], ub[4], za[4], zb[4];
            #pragma unroll
            for (int c = 0; c < 4; c++) {
                ua[c] = pk2(s_ubv[ci*60 + (pr0  )*10 + pc0 + c]);
                za[c] = pk2(s_zav[ci*60 + (pr0  )*10 + pc0 + c]);
                ub[c] = pk2(s_ubv[ci*60 + (pr0+1)*10 + pc0 + c]);
                zb[c] = pk2(s_zav[ci*60 + (pr0+1)*10 + pc0 + c]);
            }
            #pragma unroll
            for (int kh = 0; kh < 3; kh++) {
                ulonglong2 wv[3];
                #pragma unroll
                for (int kw = 0; kw < 3; kw++)
                    wv[kw] = *(const ulonglong2*)(s_wv + ((ci*9 + kh*3+kw)*32 + pairI)*4);
                #pragma unroll
                for (int kw = 0; kw < 3; kw++)
                    #pragma unroll
                    for (int px = 0; px < 2; px++) {
                        acc[0][px] = fma2(wv[kw].x, ua[px+kw], acc[0][px]);
                        acc[0][px] = fma2(wv[kw].y, za[px+kw], acc[0][px]);
                        acc[1][px] = fma2(wv[kw].x, ub[px+kw], acc[1][px]);
                        acc[1][px] = fma2(wv[kw].y, zb[px+kw], acc[1][px]);
                    }
                if (kh < 2) {
                    #pragma unroll
                    for (int c = 0; c < 4; c++) {
                        ua[c] = ub[c]; za[c] = zb[c];
                        ub[c] = pk2(s_ubv[ci*60 + (pr0+kh+2)*10 + pc0 + c]);
                        zb[c] = pk2(s_zav[ci*60 + (pr0+kh+2)*10 + pc0 + c]);
                    }
                }
            }
        }
        __syncthreads();
    }

    int co0 = 2 * pairI;
    #pragma unroll
    for (int pr = 0; pr < 2; pr++)
        #pragma unroll
        for (int px = 0; px < 2; px++) {
            int h = h0 + pr0 + pr;
            int w = w0 + pc0 + px;
            float lo, hi;
            unpk2(acc[pr][px], lo, hi);
            outA[((b*CC + co0    )*HH + h)*WW + w] = fminf(fmaxf(lo, 0.f), 1.f);
            outA[((b*CC + co0 + 1)*HH + h)*WW + w] = fminf(fmaxf(hi, 0.f), 1.f);
        }
}

// ============================================================
// final B: b_out = clip(conv(a,W_down,s2) + conv(z_b,W_bb), 0, 1) on 16x16
// 128 blocks: 8 tiles (4x8 out-px) x 16 b. thread: pair=tid&31 (2 co), 2x2 px.
// ============================================================
__global__ __launch_bounds__(256) void finalB_k(const float* __restrict__ aIn,
                                                float* __restrict__ outB)
{
    __shared__ __align__(16) float s_av[612];      // [4ci][9][17] (in region @ 2h0,2w0)
    __shared__ __align__(16) float s_zv[240];      // [4ci][6][10] (halo 1 @ h0-1,w0-1)
    __shared__ __align__(16) float s_wv[4608];     // [4ci][9tap][32pair][4]

    int tid = threadIdx.x;
    int pairI = tid & 31;
    int pb = tid >> 5;               // 0..7
    int pr0 = (pb >> 2) * 2;         // 0 or 2
    int pc0 = (pb & 3) * 2;          // 0,2,4,6
    int tile = blockIdx.x;           // 0..7
    int b    = blockIdx.z;
    int h0 = (tile >> 1) * 4, w0 = (tile & 1) * 8;   // out coords

    unsigned long long acc[2][2];
    #pragma unroll
    for (int i = 0; i < 2; i++)
        #pragma unroll
        for (int j = 0; j < 2; j++) acc[i][j] = 0ull;

    float2 pw[9];
    float  pv[4];

    auto ld_w = [&](int cc) {
        const float2* src = (const float2*)g_wB + (size_t)cc*2304 + tid;
        #pragma unroll
        for (int k = 0; k < 9; k++) pw[k] = src[k*256];
    };
    auto ld_v = [&](int cc) {
        #pragma unroll
        for (int k = 0; k < 4; k++) {
            int e = tid + k*256;
            float v = 0.f;
            if (e < 612) {                       // a tile
                int ci = e / 153; int i = e % 153;
                int r = i / 17, c = i % 17;
                int gh = 2*h0 + r, gw = 2*w0 + c;
                if (gh < HH && gw < WW)
                    v = aIn[((size_t)(b*CC + cc*4+ci)*HH + gh)*WW + gw];
            } else if (e < 852) {                // z tile
                int ez = e - 612;
                int ci = ez / 60; int i = ez % 60;
                int r = i / 10, c = i % 10;
                int gh = h0 - 1 + r, gw = w0 - 1 + c;
                if (gh >= 0 && gh < HO && gw >= 0 && gw < WO)
                    v = g_zb[((size_t)(b*CC + cc*4+ci)*HO + gh)*WO + gw];
            }
            pv[k] = v;
        }
    };

    ld_w(0); ld_v(0);

    for (int cc = 0; cc < 16; cc++) {
        {
            float2* wd = (float2*)s_wv + tid;
            #pragma unroll
            for (int k = 0; k < 9; k++) wd[k*256] = pw[k];
            #pragma unroll
            for (int k = 0; k < 4; k++) {
                int e = tid + k*256;
                if (e < 612)      s_av[e]     = pv[k];
                else if (e < 852) s_zv[e-612] = pv[k];
            }
        }
        __syncthreads();
        if (cc < 15) { ld_w(cc+1); ld_v(cc+1); }

        #pragma unroll 2
        for (int ci = 0; ci < 4; ci++) {
            #pragma unroll
            for (int kh = 0; kh < 3; kh++) {
                ulonglong2 wv[3];
                #pragma unroll
                for (int kw = 0; kw < 3; kw++)
                    wv[kw] = *(const ulonglong2*)(s_wv + ((ci*9 + kh*3+kw)*32 + pairI)*4);
                #pragma unroll
                for (int pr = 0; pr < 2; pr++) {
                    int ra = 2*(pr0 + pr) + kh;      // 0..8
                    int rz = pr0 + pr + kh;          // 0..5
                    unsigned long long va[5], vz[4];
                    #pragma unroll
                    for (int c = 0; c < 5; c++)
                        va[c] = pk2(s_av[ci*153 + ra*17 + 2*pc0 + c]);
                    #pragma unroll
                    for (int c = 0; c < 4; c++)
                        vz[c] = pk2(s_zv[ci*60 + rz*10 + pc0 + c]);
                    #pragma unroll
                    for (int kw = 0; kw < 3; kw++)
                        #pragma unroll
                        for (int px = 0; px < 2; px++) {
                            acc[pr][px] = fma2(wv[kw].x, va[2*px+kw], acc[pr][px]);
                            acc[pr][px] = fma2(wv[kw].y, vz[px+kw],   acc[pr][px]);
                        }
                }
            }
        }
        __syncthreads();
    }

    int co0 = 2 * pairI;
    #pragma unroll
    for (int pr = 0; pr < 2; pr++)
        #pragma unroll
        for (int px = 0; px < 2; px++) {
            int h = h0 + pr0 + pr;
            int w = w0 + pc0 + px;
            float lo, hi;
            unpk2(acc[pr][px], lo, hi);
            outB[((b*CC + co0    )*HO + h)*WO + w] = fminf(fmaxf(lo, 0.f), 1.f);
            outB[((b*CC + co0 + 1)*HO + h)*WO + w] = fminf(fmaxf(hi, 0.f), 1.f);
        }
}

// ============================================================
extern "C" void kernel_launch(void* const* d_in, const int* in_sizes, int n_in,
                              void* d_out, int out_size)
{
    (void)in_sizes; (void)n_in; (void)out_size;
    const float* u   = (const float*)d_in[0];
    const float* Win = (const float*)d_in[1];
    const float* Waa = (const float*)d_in[2];
    const float* Wdn = (const float*)d_in[3];
    const float* Wbb = (const float*)d_in[4];
    float* outA = (float*)d_out;                      // a: [16,64,32,32]
    float* outB = outA + BB*CC*HH*WW;                 // b: [16,64,16,16]

    cudaFuncSetAttribute(conv1_k, cudaFuncAttributeMaxDynamicSharedMemorySize, 67584);
    cudaFuncSetAttribute(conv2_k, cudaFuncAttributeMaxDynamicSharedMemorySize, 55296);

    wprep_k<<<864, 256>>>(Win, Waa, Wdn, Wbb);
    ubar_k <<<(BB*CC*HH*WW + 255)/256, 256>>>(u);
    conv1_k<<<dim3(128, 2, BB), 256, 67584>>>(u);
    conv2_k<<<dim3(32, 2, BB), 256, 55296>>>();
    finalA_k<<<dim3(32, 1, BB), 256>>>(outA);
    finalB_k<<<dim3(8, 1, BB), 256>>>(outA, outB);
}